// round 15
// baseline (speedup 1.0000x reference)
#include <cuda_runtime.h>
#include <cuda_fp16.h>
#include <cstdint>

// Problem constants
#define NN     100000
#define NFEAT  512
#define NHID   64
#define NCLS   16
#define NE_MAX 3200000

#define SCAN_T     256
#define SCAN_ELEMS 2048

// ---------------- device scratch ----------------
__device__ int    g_cnt[NN];
__device__ float  g_dis[NN];
__device__ int    g_ptr[NN + 1];
__device__ int    g_cur[NN];
__device__ int    g_srce[NE_MAX];          // src node only (weightless form)
__device__ __half g_h0h[NN * NCLS];        // u0 = dis * h0 (fp16)
__device__ __half g_bufA[NN * NCLS];
__device__ __half g_bufB[NN * NCLS];
__device__ int    g_bsum[256];
__device__ int    g_is64;

__device__ __forceinline__ uint32_t h2u(__half2 h) { return *reinterpret_cast<uint32_t*>(&h); }
__device__ __forceinline__ uint32_t smem_u32(const void* p) {
    uint32_t a;
    asm("{ .reg .u64 t; cvta.to.shared.u64 t, %1; cvt.u32.u64 %0, t; }" : "=r"(a) : "l"(p));
    return a;
}
__device__ __forceinline__ uint32_t f2tf(float f) {
    uint32_t r;
    asm("cvt.rna.tf32.f32 %0, %1;" : "=r"(r) : "f"(f));
    return r;
}
#define CP_ASYNC16(dst, src, sz) \
    asm volatile("cp.async.cg.shared.global [%0], [%1], 16, %2;" \
                 :: "r"(dst), "l"(src), "r"(sz))
#define CP_COMMIT() asm volatile("cp.async.commit_group;" ::: "memory")

// ---------------- init + edge dtype detection (merged) ----------------
__global__ void k_initdetect(const int* __restrict__ ei32, int E, int n) {
    int i = blockIdx.x * blockDim.x + threadIdx.x;
    if (i < n) g_cnt[i] = 0;
    if (blockIdx.x == 0) {
        __shared__ int nz;
        if (threadIdx.x == 0) nz = 0;
        __syncthreads();
        int lim = (E < 2048) ? E : 2048;
        int c = 0;
        for (int k = threadIdx.x; k < lim; k += blockDim.x)
            if (ei32[2 * k + 1] != 0) c++;
        atomicAdd(&nz, c);
        __syncthreads();
        if (threadIdx.x == 0) g_is64 = (nz == 0) ? 1 : 0;
    }
}
__device__ __forceinline__ int edge_at(const void* ei, size_t pos) {
    if (g_is64) return (int)((const long long*)ei)[pos];
    return ((const int*)ei)[pos];
}

// ---------------- CSR build ----------------
__global__ void k_count(const void* __restrict__ ei, int E) {
    int idx = blockIdx.x * blockDim.x + threadIdx.x;
    if (idx < E) {
        int c = edge_at(ei, (size_t)E + idx);
        if ((unsigned)c < NN) atomicAdd(&g_cnt[c], 1);
    }
}
__global__ void k_scan1(int n) {   // + produces g_dis
    __shared__ int sred[SCAN_T];
    int b = blockIdx.x, t = threadIdx.x;
    int base = b * SCAN_ELEMS + t * 8;
    int s = 0;
#pragma unroll
    for (int i = 0; i < 8; ++i) {
        int idx = base + i;
        if (idx < n) {
            int cv = g_cnt[idx];
            s += cv;
            g_dis[idx] = rsqrtf((float)(cv + 1));
        }
    }
    sred[t] = s;
    __syncthreads();
    for (int off = SCAN_T / 2; off >= 1; off >>= 1) {
        if (t < off) sred[t] += sred[t + off];
        __syncthreads();
    }
    if (t == 0) g_bsum[b] = sred[0];
}
__global__ void k_scan2(int nblk, int n) {
    if (threadIdx.x == 0 && blockIdx.x == 0) {
        int run = 0;
        for (int b = 0; b < nblk; ++b) {
            int v = g_bsum[b];
            g_bsum[b] = run;
            run += v;
        }
        g_ptr[n] = run;
    }
}
__global__ void k_scan3(int n) {
    __shared__ int ss[SCAN_T];
    int b = blockIdx.x, t = threadIdx.x;
    int base = b * SCAN_ELEMS + t * 8;
    int v[8];
    int tot = 0;
#pragma unroll
    for (int i = 0; i < 8; ++i) {
        int idx = base + i;
        v[i] = (idx < n) ? g_cnt[idx] : 0;
        tot += v[i];
    }
    ss[t] = tot;
    __syncthreads();
    for (int off = 1; off < SCAN_T; off <<= 1) {
        int a = (t >= off) ? ss[t - off] : 0;
        __syncthreads();
        ss[t] += a;
        __syncthreads();
    }
    int run = g_bsum[b] + ss[t] - tot;
#pragma unroll
    for (int i = 0; i < 8; ++i) {
        int idx = base + i;
        if (idx < n) {
            g_ptr[idx] = run;
            g_cur[idx] = run;
            run += v[i];
        }
    }
}
__global__ void k_fill(const void* __restrict__ ei, int E) {
    int idx = blockIdx.x * blockDim.x + threadIdx.x;
    if (idx < E) {
        int r = edge_at(ei, idx);
        int c = edge_at(ei, (size_t)E + idx);
        if ((unsigned)r < NN && (unsigned)c < NN) {
            int pos = atomicAdd(&g_cur[c], 1);
            g_srce[pos] = r;
        }
    }
}

// ---------------- fused MLP: cp.async double-buffer + tf32 mma (frozen) ------
#define TM 128
#define TKC 64
#define NCHUNK (NFEAT / TKC)
#define LDF  68          // fp32 stride: 68 % 32 = 4 -> (4r+q) conflict-free
#define LDA  72          // fp16 Hs stride (halfs)
#define LDW2 65

#define SMO_W2 0                           // 4160 B
#define SMO_A0 4160                        // 128*68*4 = 34816 B
#define SMO_A1 38976                       // 34816 B
#define SMO_B0 73792                       // 64*68*4 = 17408 B
#define SMO_B1 91200                       // 17408 B
#define SM_TOTAL 108608

__device__ __forceinline__ void mma_tf32(float* d, uint32_t a0, uint32_t a1,
                                         uint32_t a2, uint32_t a3,
                                         uint32_t b0, uint32_t b1) {
    asm volatile(
        "mma.sync.aligned.m16n8k8.row.col.f32.tf32.tf32.f32 "
        "{%0,%1,%2,%3}, {%4,%5,%6,%7}, {%8,%9}, {%0,%1,%2,%3};"
        : "+f"(d[0]), "+f"(d[1]), "+f"(d[2]), "+f"(d[3])
        : "r"(a0), "r"(a1), "r"(a2), "r"(a3), "r"(b0), "r"(b1));
}

__global__ __launch_bounds__(256) void k_gemm(const float* __restrict__ x,
                                              const float* __restrict__ W1,
                                              const float* __restrict__ b1,
                                              const float* __restrict__ W2,
                                              const float* __restrict__ b2,
                                              int n) {
    extern __shared__ __align__(16) unsigned char sm[];
    float* W2s = (float*)(sm + SMO_W2);
    const uint32_t smb = smem_u32(sm);

    const int t = threadIdx.x, wid = t >> 5, lane = t & 31;
    const int warpM = wid & 3, warpN = wid >> 2;
    const int r = lane >> 2, q = lane & 3;
    const int nodeBase = blockIdx.x * TM;

    for (int i = t; i < NCLS * NHID; i += 256)
        W2s[(i >> 6) * LDW2 + (i & 63)] = W2[i];

#define ISSUE(c, buf)                                                          \
    {                                                                          \
        uint32_t abase = smb + ((buf) ? SMO_A1 : SMO_A0);                      \
        uint32_t bbase = smb + ((buf) ? SMO_B1 : SMO_B0);                      \
        _Pragma("unroll") for (int i = 0; i < 8; ++i) {                        \
            int slot = t + i * 256;                                            \
            int row = slot >> 4, f4 = slot & 15;                               \
            int gn = nodeBase + row;                                           \
            int gc = (gn < n) ? gn : (n - 1);                                  \
            const float* src = x + (size_t)gc * NFEAT + (c) * TKC + f4 * 4;    \
            CP_ASYNC16(abase + (uint32_t)(row * LDF + f4 * 4) * 4, src,        \
                       (gn < n) ? 16 : 0);                                     \
        }                                                                      \
        _Pragma("unroll") for (int i = 0; i < 4; ++i) {                        \
            int slot = t + i * 256;                                            \
            int row = slot >> 4, f4 = slot & 15;                               \
            const float* src = W1 + (size_t)row * NFEAT + (c) * TKC + f4 * 4;  \
            CP_ASYNC16(bbase + (uint32_t)(row * LDF + f4 * 4) * 4, src, 16);   \
        }                                                                      \
        CP_COMMIT();                                                           \
    }

    float acc[2][4][4];
#pragma unroll
    for (int mt = 0; mt < 2; ++mt)
#pragma unroll
        for (int nt = 0; nt < 4; ++nt)
#pragma unroll
            for (int j = 0; j < 4; ++j) acc[mt][nt][j] = 0.f;

    ISSUE(0, 0);
    ISSUE(1, 1);

    for (int c = 0; c < NCHUNK; ++c) {
        if (c == NCHUNK - 1)
            asm volatile("cp.async.wait_group 0;" ::: "memory");
        else
            asm volatile("cp.async.wait_group 1;" ::: "memory");
        __syncthreads();
        const float* As = (const float*)(sm + ((c & 1) ? SMO_A1 : SMO_A0));
        const float* Bs = (const float*)(sm + ((c & 1) ? SMO_B1 : SMO_B0));
#pragma unroll
        for (int ks = 0; ks < TKC / 8; ++ks) {
            int kc = ks * 8 + q;
            uint32_t bf[4][2];
#pragma unroll
            for (int nt = 0; nt < 4; ++nt) {
                int nr = warpN * 32 + nt * 8 + r;
                bf[nt][0] = f2tf(Bs[nr * LDF + kc]);
                bf[nt][1] = f2tf(Bs[nr * LDF + kc + 4]);
            }
#pragma unroll
            for (int mt = 0; mt < 2; ++mt) {
                int mr = warpM * 32 + mt * 16 + r;
                uint32_t a0 = f2tf(As[mr * LDF + kc]);
                uint32_t a1 = f2tf(As[(mr + 8) * LDF + kc]);
                uint32_t a2 = f2tf(As[mr * LDF + kc + 4]);
                uint32_t a3 = f2tf(As[(mr + 8) * LDF + kc + 4]);
#pragma unroll
                for (int nt = 0; nt < 4; ++nt)
                    mma_tf32(acc[mt][nt], a0, a1, a2, a3, bf[nt][0], bf[nt][1]);
            }
        }
        __syncthreads();
        if (c + 2 < NCHUNK) ISSUE(c + 2, c & 1);
    }

    // ---- epilogue: relu+bias -> Hs fp16 (A0 region), GEMM2, u0 = dis*h0 ----
    __half* Hs = (__half*)(sm + SMO_A0);
#pragma unroll
    for (int mt = 0; mt < 2; ++mt) {
        int r0 = warpM * 32 + mt * 16 + r;
#pragma unroll
        for (int nt = 0; nt < 4; ++nt) {
            int col = warpN * 32 + nt * 8 + q * 2;
            float bb0 = b1[col], bb1 = b1[col + 1];
            float* a = acc[mt][nt];
            __half2 lo = __floats2half2_rn(fmaxf(a[0] + bb0, 0.f), fmaxf(a[1] + bb1, 0.f));
            __half2 hi = __floats2half2_rn(fmaxf(a[2] + bb0, 0.f), fmaxf(a[3] + bb1, 0.f));
            *(__half2*)(Hs + (size_t)r0 * LDA + col)       = lo;
            *(__half2*)(Hs + (size_t)(r0 + 8) * LDA + col) = hi;
        }
    }
    __syncthreads();

    int cls = t & 15, grp = t >> 4;
    float bc = b2[cls];
#pragma unroll
    for (int i = 0; i < 8; ++i) {
        int row = grp * 8 + i;
        int gn = nodeBase + row;
        float a = bc;
        const __half2* hr = (const __half2*)(Hs + (size_t)row * LDA);
#pragma unroll
        for (int k = 0; k < 32; ++k) {
            float2 f = __half22float2(hr[k]);
            a = fmaf(f.x, W2s[cls * LDW2 + 2 * k], a);
            a = fmaf(f.y, W2s[cls * LDW2 + 2 * k + 1], a);
        }
        if (gn < n)
            g_h0h[(size_t)gn * NCLS + cls] = __float2half_rn(a * g_dis[gn]);  // u0
    }
#undef ISSUE
}

// ---------------- APPNP step: warp-cooperative, divergence-free --------------
// Warp processes 8 nodes sequentially; all 32 lanes (8 edge-slots x 4
// row-quarters) gather edges of the SAME node each iteration, so work per
// warp is sum(ceil(deg/8)) (balanced) instead of max-driven.
// u_new_c = 0.9*dis_c^2 * (sum_in u_r + u_c) + 0.1*u0_c
__global__ __launch_bounds__(256) void k_prop(int srcSel, int dstSel, int n) {
    int warpId = (blockIdx.x * 256 + threadIdx.x) >> 5;
    int lane = threadIdx.x & 31;
    int sub = lane >> 2;       // edge slot 0..7
    int lpos = lane & 3;       // quarter-row (uint2 = 4 classes)
    int nd0 = warpId * 8;
    if (nd0 >= n) return;
    const uint2* __restrict__ hin = (const uint2*)(
        (srcSel == 0) ? g_h0h : ((srcSel == 1) ? g_bufA : g_bufB));
    uint2* __restrict__ hout = (uint2*)((dstSel == 1) ? g_bufA : g_bufB);

    int ndEnd = (nd0 + 8 < n) ? nd0 + 8 : n;
    for (int nd = nd0; nd < ndEnd; ++nd) {      // warp-uniform trip count
        int start = g_ptr[nd], end = g_ptr[nd + 1];
        float a0 = 0.f, a1 = 0.f, a2 = 0.f, a3 = 0.f;
        for (int base = start; base < end; base += 8) {
            int e = base + sub;
            int s = (e < end) ? __ldg(&g_srce[e]) : -1;
            if (s >= 0) {
                uint2 u = __ldg(hin + (size_t)s * 4 + lpos);
                float2 f0 = __half22float2(*(__half2*)&u.x);
                float2 f1 = __half22float2(*(__half2*)&u.y);
                a0 += f0.x; a1 += f0.y; a2 += f1.x; a3 += f1.y;
            }
        }
        // reduce across the 8 edge-slots (lanes with equal lpos)
#pragma unroll
        for (int off = 16; off >= 4; off >>= 1) {
            a0 += __shfl_xor_sync(0xFFFFFFFFu, a0, off);
            a1 += __shfl_xor_sync(0xFFFFFFFFu, a1, off);
            a2 += __shfl_xor_sync(0xFFFFFFFFu, a2, off);
            a3 += __shfl_xor_sync(0xFFFFFFFFu, a3, off);
        }
        if (sub == 0) {
            uint2 u = hin[(size_t)nd * 4 + lpos];        // self loop (u_c)
            float2 f0 = __half22float2(*(__half2*)&u.x);
            float2 f1 = __half22float2(*(__half2*)&u.y);
            a0 += f0.x; a1 += f0.y; a2 += f1.x; a3 += f1.y;
            float dv = g_dis[nd];
            float sc = 0.9f * dv * dv;
            uint2 uz = ((const uint2*)g_h0h)[(size_t)nd * 4 + lpos];
            float2 z0 = __half22float2(*(__half2*)&uz.x);
            float2 z1 = __half22float2(*(__half2*)&uz.y);
            uint2 o;
            o.x = h2u(__floats2half2_rn(fmaf(sc, a0, 0.1f * z0.x),
                                        fmaf(sc, a1, 0.1f * z0.y)));
            o.y = h2u(__floats2half2_rn(fmaf(sc, a2, 0.1f * z1.x),
                                        fmaf(sc, a3, 0.1f * z1.y)));
            hout[(size_t)nd * 4 + lpos] = o;
        }
    }
}

// ---------------- log-softmax (thread per node, un-scale u -> h) -------------
__global__ void k_lsm(float* __restrict__ out, int n) {
    int nd = blockIdx.x * blockDim.x + threadIdx.x;
    if (nd >= n) return;
    const __half2* hb = (const __half2*)g_bufB + (size_t)nd * 8;
    float inv = 1.0f / g_dis[nd];
    float v[16];
#pragma unroll
    for (int i = 0; i < 8; ++i) {
        float2 f = __half22float2(hb[i]);
        v[2 * i] = f.x * inv;
        v[2 * i + 1] = f.y * inv;
    }
    float m = v[0];
#pragma unroll
    for (int i = 1; i < 16; ++i) m = fmaxf(m, v[i]);
    float s = 0.f;
#pragma unroll
    for (int i = 0; i < 16; ++i) s += expf(v[i] - m);
    float ls = m + logf(s);
    float* o = out + (size_t)nd * 16;
#pragma unroll
    for (int i = 0; i < 16; i += 4) {
        float4 qv = make_float4(v[i] - ls, v[i + 1] - ls, v[i + 2] - ls, v[i + 3] - ls);
        *(float4*)(o + i) = qv;
    }
}

// ---------------- launch (serial, single stream) -----------------------------
extern "C" void kernel_launch(void* const* d_in, const int* in_sizes, int n_in,
                              void* d_out, int out_size) {
    const float* x  = (const float*)d_in[0];
    const float* W1 = (const float*)d_in[1];
    const float* b1 = (const float*)d_in[2];
    const float* W2 = (const float*)d_in[3];
    const float* b2 = (const float*)d_in[4];
    const void*  ei = d_in[5];
    float* out = (float*)d_out;

    int N = in_sizes[0] / NFEAT;
    int E = in_sizes[5] / 2;
    int sblocks = (N + SCAN_ELEMS - 1) / SCAN_ELEMS;

    static int attr_set = 0;
    if (!attr_set) {
        cudaFuncSetAttribute(k_gemm, cudaFuncAttributeMaxDynamicSharedMemorySize,
                             SM_TOTAL);
        attr_set = 1;
    }

    // launch index 3 (ncu capture) = k_gemm
    k_initdetect<<<(N + 255) / 256, 256>>>((const int*)ei, E, N);       // 0
    k_count<<<(E + 255) / 256, 256>>>(ei, E);                           // 1
    k_scan1<<<sblocks, SCAN_T>>>(N);                                    // 2
    k_gemm<<<(N + TM - 1) / TM, 256, SM_TOTAL>>>(x, W1, b1, W2, b2, N); // 3
    k_scan2<<<1, 32>>>(sblocks, N);                                     // 4
    k_scan3<<<sblocks, SCAN_T>>>(N);                                    // 5
    k_fill<<<(E + 255) / 256, 256>>>(ei, E);                            // 6

    // warp = 8 nodes; block = 256 thr = 8 warps = 64 nodes
    int pgrid = (N + 63) / 64;
    int src = 0;
    for (int step = 1; step <= 10; ++step) {
        int dst = (step & 1) ? 1 : 2;
        k_prop<<<pgrid, 256>>>(src, dst, N);
        src = dst;
    }
    k_lsm<<<(N + 255) / 256, 256>>>(out, N);
}

// round 16
// speedup vs baseline: 1.5451x; 1.5451x over previous
#include <cuda_runtime.h>
#include <cuda_fp16.h>
#include <cstdint>

// Problem constants
#define NN     100000
#define NFEAT  512
#define NHID   64
#define NCLS   16
#define NE_MAX 3200000

#define SCAN_T     256
#define SCAN_ELEMS 2048

// ---------------- device scratch ----------------
__device__ int    g_cnt[NN];
__device__ float  g_dis[NN];
__device__ int    g_ptr[NN + 1];
__device__ int    g_cur[NN];
__device__ int    g_srce[NE_MAX];          // src node only (weightless form)
__device__ __half g_h0h[NN * NCLS];        // u0 = dis * h0 (fp16)
__device__ __half g_bufA[NN * NCLS];
__device__ __half g_bufB[NN * NCLS];
__device__ int    g_bsum[256];
__device__ int    g_is64;

__device__ __forceinline__ uint32_t h2u(__half2 h) { return *reinterpret_cast<uint32_t*>(&h); }
__device__ __forceinline__ uint32_t smem_u32(const void* p) {
    uint32_t a;
    asm("{ .reg .u64 t; cvta.to.shared.u64 t, %1; cvt.u32.u64 %0, t; }" : "=r"(a) : "l"(p));
    return a;
}
__device__ __forceinline__ uint32_t f2tf(float f) {
    uint32_t r;
    asm("cvt.rna.tf32.f32 %0, %1;" : "=r"(r) : "f"(f));
    return r;
}
#define CP_ASYNC16(dst, src, sz) \
    asm volatile("cp.async.cg.shared.global [%0], [%1], 16, %2;" \
                 :: "r"(dst), "l"(src), "r"(sz))
#define CP_COMMIT() asm volatile("cp.async.commit_group;" ::: "memory")

// ---------------- init + edge dtype detection (merged) ----------------
__global__ void k_initdetect(const int* __restrict__ ei32, int E, int n) {
    int i = blockIdx.x * blockDim.x + threadIdx.x;
    if (i < n) g_cnt[i] = 0;
    if (blockIdx.x == 0) {
        __shared__ int nz;
        if (threadIdx.x == 0) nz = 0;
        __syncthreads();
        int lim = (E < 2048) ? E : 2048;
        int c = 0;
        for (int k = threadIdx.x; k < lim; k += blockDim.x)
            if (ei32[2 * k + 1] != 0) c++;
        atomicAdd(&nz, c);
        __syncthreads();
        if (threadIdx.x == 0) g_is64 = (nz == 0) ? 1 : 0;
    }
}
__device__ __forceinline__ int edge_at(const void* ei, size_t pos) {
    if (g_is64) return (int)((const long long*)ei)[pos];
    return ((const int*)ei)[pos];
}

// ---------------- CSR build ----------------
__global__ void k_count(const void* __restrict__ ei, int E) {
    int idx = blockIdx.x * blockDim.x + threadIdx.x;
    if (idx < E) {
        int c = edge_at(ei, (size_t)E + idx);
        if ((unsigned)c < NN) atomicAdd(&g_cnt[c], 1);
    }
}
__global__ void k_scan1(int n) {   // + produces g_dis
    __shared__ int sred[SCAN_T];
    int b = blockIdx.x, t = threadIdx.x;
    int base = b * SCAN_ELEMS + t * 8;
    int s = 0;
#pragma unroll
    for (int i = 0; i < 8; ++i) {
        int idx = base + i;
        if (idx < n) {
            int cv = g_cnt[idx];
            s += cv;
            g_dis[idx] = rsqrtf((float)(cv + 1));
        }
    }
    sred[t] = s;
    __syncthreads();
    for (int off = SCAN_T / 2; off >= 1; off >>= 1) {
        if (t < off) sred[t] += sred[t + off];
        __syncthreads();
    }
    if (t == 0) g_bsum[b] = sred[0];
}
__global__ void k_scan2(int nblk, int n) {
    if (threadIdx.x == 0 && blockIdx.x == 0) {
        int run = 0;
        for (int b = 0; b < nblk; ++b) {
            int v = g_bsum[b];
            g_bsum[b] = run;
            run += v;
        }
        g_ptr[n] = run;
    }
}
__global__ void k_scan3(int n) {
    __shared__ int ss[SCAN_T];
    int b = blockIdx.x, t = threadIdx.x;
    int base = b * SCAN_ELEMS + t * 8;
    int v[8];
    int tot = 0;
#pragma unroll
    for (int i = 0; i < 8; ++i) {
        int idx = base + i;
        v[i] = (idx < n) ? g_cnt[idx] : 0;
        tot += v[i];
    }
    ss[t] = tot;
    __syncthreads();
    for (int off = 1; off < SCAN_T; off <<= 1) {
        int a = (t >= off) ? ss[t - off] : 0;
        __syncthreads();
        ss[t] += a;
        __syncthreads();
    }
    int run = g_bsum[b] + ss[t] - tot;
#pragma unroll
    for (int i = 0; i < 8; ++i) {
        int idx = base + i;
        if (idx < n) {
            g_ptr[idx] = run;
            g_cur[idx] = run;
            run += v[i];
        }
    }
}
__global__ void k_fill(const void* __restrict__ ei, int E) {
    int idx = blockIdx.x * blockDim.x + threadIdx.x;
    if (idx < E) {
        int r = edge_at(ei, idx);
        int c = edge_at(ei, (size_t)E + idx);
        if ((unsigned)r < NN && (unsigned)c < NN) {
            int pos = atomicAdd(&g_cur[c], 1);
            g_srce[pos] = r;
        }
    }
}

// ---------------- fused MLP: cp.async double-buffer + tf32 mma (frozen) ------
#define TM 128
#define TKC 64
#define NCHUNK (NFEAT / TKC)
#define LDF  68          // fp32 stride: 68 % 32 = 4 -> (4r+q) conflict-free
#define LDA  72          // fp16 Hs stride (halfs)
#define LDW2 65

#define SMO_W2 0                           // 4160 B
#define SMO_A0 4160                        // 128*68*4 = 34816 B
#define SMO_A1 38976                       // 34816 B
#define SMO_B0 73792                       // 64*68*4 = 17408 B
#define SMO_B1 91200                       // 17408 B
#define SM_TOTAL 108608

__device__ __forceinline__ void mma_tf32(float* d, uint32_t a0, uint32_t a1,
                                         uint32_t a2, uint32_t a3,
                                         uint32_t b0, uint32_t b1) {
    asm volatile(
        "mma.sync.aligned.m16n8k8.row.col.f32.tf32.tf32.f32 "
        "{%0,%1,%2,%3}, {%4,%5,%6,%7}, {%8,%9}, {%0,%1,%2,%3};"
        : "+f"(d[0]), "+f"(d[1]), "+f"(d[2]), "+f"(d[3])
        : "r"(a0), "r"(a1), "r"(a2), "r"(a3), "r"(b0), "r"(b1));
}

__global__ __launch_bounds__(256) void k_gemm(const float* __restrict__ x,
                                              const float* __restrict__ W1,
                                              const float* __restrict__ b1,
                                              const float* __restrict__ W2,
                                              const float* __restrict__ b2,
                                              int n) {
    extern __shared__ __align__(16) unsigned char sm[];
    float* W2s = (float*)(sm + SMO_W2);
    const uint32_t smb = smem_u32(sm);

    const int t = threadIdx.x, wid = t >> 5, lane = t & 31;
    const int warpM = wid & 3, warpN = wid >> 2;
    const int r = lane >> 2, q = lane & 3;
    const int nodeBase = blockIdx.x * TM;

    for (int i = t; i < NCLS * NHID; i += 256)
        W2s[(i >> 6) * LDW2 + (i & 63)] = W2[i];

#define ISSUE(c, buf)                                                          \
    {                                                                          \
        uint32_t abase = smb + ((buf) ? SMO_A1 : SMO_A0);                      \
        uint32_t bbase = smb + ((buf) ? SMO_B1 : SMO_B0);                      \
        _Pragma("unroll") for (int i = 0; i < 8; ++i) {                        \
            int slot = t + i * 256;                                            \
            int row = slot >> 4, f4 = slot & 15;                               \
            int gn = nodeBase + row;                                           \
            int gc = (gn < n) ? gn : (n - 1);                                  \
            const float* src = x + (size_t)gc * NFEAT + (c) * TKC + f4 * 4;    \
            CP_ASYNC16(abase + (uint32_t)(row * LDF + f4 * 4) * 4, src,        \
                       (gn < n) ? 16 : 0);                                     \
        }                                                                      \
        _Pragma("unroll") for (int i = 0; i < 4; ++i) {                        \
            int slot = t + i * 256;                                            \
            int row = slot >> 4, f4 = slot & 15;                               \
            const float* src = W1 + (size_t)row * NFEAT + (c) * TKC + f4 * 4;  \
            CP_ASYNC16(bbase + (uint32_t)(row * LDF + f4 * 4) * 4, src, 16);   \
        }                                                                      \
        CP_COMMIT();                                                           \
    }

    float acc[2][4][4];
#pragma unroll
    for (int mt = 0; mt < 2; ++mt)
#pragma unroll
        for (int nt = 0; nt < 4; ++nt)
#pragma unroll
            for (int j = 0; j < 4; ++j) acc[mt][nt][j] = 0.f;

    ISSUE(0, 0);
    ISSUE(1, 1);

    for (int c = 0; c < NCHUNK; ++c) {
        if (c == NCHUNK - 1)
            asm volatile("cp.async.wait_group 0;" ::: "memory");
        else
            asm volatile("cp.async.wait_group 1;" ::: "memory");
        __syncthreads();
        const float* As = (const float*)(sm + ((c & 1) ? SMO_A1 : SMO_A0));
        const float* Bs = (const float*)(sm + ((c & 1) ? SMO_B1 : SMO_B0));
#pragma unroll
        for (int ks = 0; ks < TKC / 8; ++ks) {
            int kc = ks * 8 + q;
            uint32_t bf[4][2];
#pragma unroll
            for (int nt = 0; nt < 4; ++nt) {
                int nr = warpN * 32 + nt * 8 + r;
                bf[nt][0] = f2tf(Bs[nr * LDF + kc]);
                bf[nt][1] = f2tf(Bs[nr * LDF + kc + 4]);
            }
#pragma unroll
            for (int mt = 0; mt < 2; ++mt) {
                int mr = warpM * 32 + mt * 16 + r;
                uint32_t a0 = f2tf(As[mr * LDF + kc]);
                uint32_t a1 = f2tf(As[(mr + 8) * LDF + kc]);
                uint32_t a2 = f2tf(As[mr * LDF + kc + 4]);
                uint32_t a3 = f2tf(As[(mr + 8) * LDF + kc + 4]);
#pragma unroll
                for (int nt = 0; nt < 4; ++nt)
                    mma_tf32(acc[mt][nt], a0, a1, a2, a3, bf[nt][0], bf[nt][1]);
            }
        }
        __syncthreads();
        if (c + 2 < NCHUNK) ISSUE(c + 2, c & 1);
    }

    // ---- epilogue: relu+bias -> Hs fp16 (A0 region), GEMM2, u0 = dis*h0 ----
    __half* Hs = (__half*)(sm + SMO_A0);
#pragma unroll
    for (int mt = 0; mt < 2; ++mt) {
        int r0 = warpM * 32 + mt * 16 + r;
#pragma unroll
        for (int nt = 0; nt < 4; ++nt) {
            int col = warpN * 32 + nt * 8 + q * 2;
            float bb0 = b1[col], bb1 = b1[col + 1];
            float* a = acc[mt][nt];
            __half2 lo = __floats2half2_rn(fmaxf(a[0] + bb0, 0.f), fmaxf(a[1] + bb1, 0.f));
            __half2 hi = __floats2half2_rn(fmaxf(a[2] + bb0, 0.f), fmaxf(a[3] + bb1, 0.f));
            *(__half2*)(Hs + (size_t)r0 * LDA + col)       = lo;
            *(__half2*)(Hs + (size_t)(r0 + 8) * LDA + col) = hi;
        }
    }
    __syncthreads();

    int cls = t & 15, grp = t >> 4;
    float bc = b2[cls];
#pragma unroll
    for (int i = 0; i < 8; ++i) {
        int row = grp * 8 + i;
        int gn = nodeBase + row;
        float a = bc;
        const __half2* hr = (const __half2*)(Hs + (size_t)row * LDA);
#pragma unroll
        for (int k = 0; k < 32; ++k) {
            float2 f = __half22float2(hr[k]);
            a = fmaf(f.x, W2s[cls * LDW2 + 2 * k], a);
            a = fmaf(f.y, W2s[cls * LDW2 + 2 * k + 1], a);
        }
        if (gn < n)
            g_h0h[(size_t)gn * NCLS + cls] = __float2half_rn(a * g_dis[gn]);  // u0
    }
#undef ISSUE
}

// ---------------- APPNP step: 4 lanes/node, shfl-free broadcast edge loads ---
// All 4 lanes of a node-group load the same sequential edge indices directly
// (L1 broadcast) — no cross-lane shfl in the gather chain, 8-edge batches for
// MLP. Accumulation order identical to the R12 version (even j -> a, odd -> c).
// u_new_c = 0.9*dis_c^2 * (sum_in u_r + u_c) + 0.1*u0_c
__global__ __launch_bounds__(256) void k_prop(int srcSel, int dstSel, int n) {
    int t = blockIdx.x * 256 + threadIdx.x;
    int node = t >> 2, lane = t & 3;
    bool valid = node < n;
    if (!valid) node = n - 1;
    const uint2* __restrict__ hin = (const uint2*)(
        (srcSel == 0) ? g_h0h : ((srcSel == 1) ? g_bufA : g_bufB));
    uint2* __restrict__ hout = (uint2*)((dstSel == 1) ? g_bufA : g_bufB);

    int start = g_ptr[node], end = g_ptr[node + 1];
    float ax0 = 0.f, ax1 = 0.f, ax2 = 0.f, ax3 = 0.f;
    float cx0 = 0.f, cx1 = 0.f, cx2 = 0.f, cx3 = 0.f;

#define GATHER(sv, A0, A1, A2, A3)                                    \
    {                                                                 \
        uint2 u = __ldg(hin + (size_t)(sv) * 4 + lane);               \
        float2 f0 = __half22float2(*(__half2*)&u.x);                  \
        float2 f1 = __half22float2(*(__half2*)&u.y);                  \
        A0 += f0.x; A1 += f0.y; A2 += f1.x; A3 += f1.y;               \
    }

    for (int base = start; base < end; base += 8) {
        int s0 = __ldg(&g_srce[base]);
        int s1 = (base + 1 < end) ? __ldg(&g_srce[base + 1]) : -1;
        int s2 = (base + 2 < end) ? __ldg(&g_srce[base + 2]) : -1;
        int s3 = (base + 3 < end) ? __ldg(&g_srce[base + 3]) : -1;
        int s4 = (base + 4 < end) ? __ldg(&g_srce[base + 4]) : -1;
        int s5 = (base + 5 < end) ? __ldg(&g_srce[base + 5]) : -1;
        int s6 = (base + 6 < end) ? __ldg(&g_srce[base + 6]) : -1;
        int s7 = (base + 7 < end) ? __ldg(&g_srce[base + 7]) : -1;
        GATHER(s0, ax0, ax1, ax2, ax3);
        if (s1 >= 0) GATHER(s1, cx0, cx1, cx2, cx3);
        if (s2 >= 0) GATHER(s2, ax0, ax1, ax2, ax3);
        if (s3 >= 0) GATHER(s3, cx0, cx1, cx2, cx3);
        if (s4 >= 0) GATHER(s4, ax0, ax1, ax2, ax3);
        if (s5 >= 0) GATHER(s5, cx0, cx1, cx2, cx3);
        if (s6 >= 0) GATHER(s6, ax0, ax1, ax2, ax3);
        if (s7 >= 0) GATHER(s7, cx0, cx1, cx2, cx3);
    }
#undef GATHER
    ax0 += cx0; ax1 += cx1; ax2 += cx2; ax3 += cx3;
    {
        uint2 u = hin[(size_t)node * 4 + lane];          // self loop (u_c)
        float2 f0 = __half22float2(*(__half2*)&u.x);
        float2 f1 = __half22float2(*(__half2*)&u.y);
        ax0 += f0.x; ax1 += f0.y; ax2 += f1.x; ax3 += f1.y;
    }
    float dv = g_dis[node];
    float s = 0.9f * dv * dv;
    uint2 uz = ((const uint2*)g_h0h)[(size_t)node * 4 + lane];
    float2 z0 = __half22float2(*(__half2*)&uz.x);
    float2 z1 = __half22float2(*(__half2*)&uz.y);
    float r0 = fmaf(s, ax0, 0.1f * z0.x);
    float r1 = fmaf(s, ax1, 0.1f * z0.y);
    float r2 = fmaf(s, ax2, 0.1f * z1.x);
    float r3 = fmaf(s, ax3, 0.1f * z1.y);
    if (valid) {
        uint2 o;
        o.x = h2u(__floats2half2_rn(r0, r1));
        o.y = h2u(__floats2half2_rn(r2, r3));
        hout[(size_t)node * 4 + lane] = o;
    }
}

// ---------------- log-softmax (thread per node, un-scale u -> h) -------------
__global__ void k_lsm(float* __restrict__ out, int n) {
    int nd = blockIdx.x * blockDim.x + threadIdx.x;
    if (nd >= n) return;
    const __half2* hb = (const __half2*)g_bufB + (size_t)nd * 8;
    float inv = 1.0f / g_dis[nd];
    float v[16];
#pragma unroll
    for (int i = 0; i < 8; ++i) {
        float2 f = __half22float2(hb[i]);
        v[2 * i] = f.x * inv;
        v[2 * i + 1] = f.y * inv;
    }
    float m = v[0];
#pragma unroll
    for (int i = 1; i < 16; ++i) m = fmaxf(m, v[i]);
    float s = 0.f;
#pragma unroll
    for (int i = 0; i < 16; ++i) s += expf(v[i] - m);
    float ls = m + logf(s);
    float* o = out + (size_t)nd * 16;
#pragma unroll
    for (int i = 0; i < 16; i += 4) {
        float4 qv = make_float4(v[i] - ls, v[i + 1] - ls, v[i + 2] - ls, v[i + 3] - ls);
        *(float4*)(o + i) = qv;
    }
}

// ---------------- launch (serial, single stream — R12 structure) -------------
extern "C" void kernel_launch(void* const* d_in, const int* in_sizes, int n_in,
                              void* d_out, int out_size) {
    const float* x  = (const float*)d_in[0];
    const float* W1 = (const float*)d_in[1];
    const float* b1 = (const float*)d_in[2];
    const float* W2 = (const float*)d_in[3];
    const float* b2 = (const float*)d_in[4];
    const void*  ei = d_in[5];
    float* out = (float*)d_out;

    int N = in_sizes[0] / NFEAT;
    int E = in_sizes[5] / 2;
    int sblocks = (N + SCAN_ELEMS - 1) / SCAN_ELEMS;

    static int attr_set = 0;
    if (!attr_set) {
        cudaFuncSetAttribute(k_gemm, cudaFuncAttributeMaxDynamicSharedMemorySize,
                             SM_TOTAL);
        attr_set = 1;
    }

    k_initdetect<<<(N + 255) / 256, 256>>>((const int*)ei, E, N);       // 0
    k_count<<<(E + 255) / 256, 256>>>(ei, E);                           // 1
    k_scan1<<<sblocks, SCAN_T>>>(N);                                    // 2
    k_gemm<<<(N + TM - 1) / TM, 256, SM_TOTAL>>>(x, W1, b1, W2, b2, N); // 3
    k_scan2<<<1, 32>>>(sblocks, N);                                     // 4
    k_scan3<<<sblocks, SCAN_T>>>(N);                                    // 5
    k_fill<<<(E + 255) / 256, 256>>>(ei, E);                            // 6

    int grid = (N * 4 + 255) / 256;
    int src = 0;
    for (int step = 1; step <= 10; ++step) {
        int dst = (step & 1) ? 1 : 2;
        k_prop<<<grid, 256>>>(src, dst, N);
        src = dst;
    }
    k_lsm<<<(N + 255) / 256, 256>>>(out, N);
}

// round 17
// speedup vs baseline: 1.6100x; 1.0420x over previous
#include <cuda_runtime.h>
#include <cuda_fp16.h>
#include <cstdint>

// Problem constants
#define NN     100000
#define NFEAT  512
#define NHID   64
#define NCLS   16
#define NE_MAX 3200000

#define SCAN_T     256
#define SCAN_ELEMS 2048

// ---------------- device scratch ----------------
__device__ int    g_cnt[NN];
__device__ float  g_dis[NN];
__device__ int    g_ptr[NN + 1];
__device__ int    g_cur[NN];
__device__ int    g_srce[NE_MAX];          // src node only (weightless form)
__device__ __half g_h0h[NN * NCLS];        // u0 = dis * h0 (fp16)
__device__ __half g_bufA[NN * NCLS];
__device__ __half g_bufB[NN * NCLS];
__device__ int    g_bsum[256];
__device__ int    g_is64;

__device__ __forceinline__ uint32_t h2u(__half2 h) { return *reinterpret_cast<uint32_t*>(&h); }
__device__ __forceinline__ uint32_t smem_u32(const void* p) {
    uint32_t a;
    asm("{ .reg .u64 t; cvta.to.shared.u64 t, %1; cvt.u32.u64 %0, t; }" : "=r"(a) : "l"(p));
    return a;
}
#define CP_ASYNC16(dst, src, sz) \
    asm volatile("cp.async.cg.shared.global [%0], [%1], 16, %2;" \
                 :: "r"(dst), "l"(src), "r"(sz))
#define CP_COMMIT() asm volatile("cp.async.commit_group;" ::: "memory")

// ---------------- init + edge dtype detection (merged) ----------------
__global__ void k_initdetect(const int* __restrict__ ei32, int E, int n) {
    int i = blockIdx.x * blockDim.x + threadIdx.x;
    if (i < n) g_cnt[i] = 0;
    if (blockIdx.x == 0) {
        __shared__ int nz;
        if (threadIdx.x == 0) nz = 0;
        __syncthreads();
        int lim = (E < 2048) ? E : 2048;
        int c = 0;
        for (int k = threadIdx.x; k < lim; k += blockDim.x)
            if (ei32[2 * k + 1] != 0) c++;
        atomicAdd(&nz, c);
        __syncthreads();
        if (threadIdx.x == 0) g_is64 = (nz == 0) ? 1 : 0;
    }
}
__device__ __forceinline__ int edge_at(const void* ei, size_t pos) {
    if (g_is64) return (int)((const long long*)ei)[pos];
    return ((const int*)ei)[pos];
}

// ---------------- CSR build ----------------
__global__ void k_count(const void* __restrict__ ei, int E) {
    int idx = blockIdx.x * blockDim.x + threadIdx.x;
    if (idx < E) {
        int c = edge_at(ei, (size_t)E + idx);
        if ((unsigned)c < NN) atomicAdd(&g_cnt[c], 1);
    }
}
__global__ void k_scan1(int n) {   // + produces g_dis
    __shared__ int sred[SCAN_T];
    int b = blockIdx.x, t = threadIdx.x;
    int base = b * SCAN_ELEMS + t * 8;
    int s = 0;
#pragma unroll
    for (int i = 0; i < 8; ++i) {
        int idx = base + i;
        if (idx < n) {
            int cv = g_cnt[idx];
            s += cv;
            g_dis[idx] = rsqrtf((float)(cv + 1));
        }
    }
    sred[t] = s;
    __syncthreads();
    for (int off = SCAN_T / 2; off >= 1; off >>= 1) {
        if (t < off) sred[t] += sred[t + off];
        __syncthreads();
    }
    if (t == 0) g_bsum[b] = sred[0];
}
// scan3 with scan2 folded in: each block prefixes the block sums itself.
__global__ void k_scan3(int nblk, int n) {
    __shared__ int ss[SCAN_T];
    __shared__ int bpre;
    int b = blockIdx.x, t = threadIdx.x;
    if (t == 0) {
        int run = 0;
        for (int i = 0; i < b; ++i) run += g_bsum[i];
        bpre = run;
        if (b == nblk - 1) {                 // total E for g_ptr[n]
            int tot = run;
            for (int i = b; i < nblk; ++i) tot += g_bsum[i];
            g_ptr[n] = tot;
        }
    }
    int base = b * SCAN_ELEMS + t * 8;
    int v[8];
    int tot = 0;
#pragma unroll
    for (int i = 0; i < 8; ++i) {
        int idx = base + i;
        v[i] = (idx < n) ? g_cnt[idx] : 0;
        tot += v[i];
    }
    ss[t] = tot;
    __syncthreads();
    for (int off = 1; off < SCAN_T; off <<= 1) {
        int a = (t >= off) ? ss[t - off] : 0;
        __syncthreads();
        ss[t] += a;
        __syncthreads();
    }
    int run = bpre + ss[t] - tot;
#pragma unroll
    for (int i = 0; i < 8; ++i) {
        int idx = base + i;
        if (idx < n) {
            g_ptr[idx] = run;
            g_cur[idx] = run;
            run += v[i];
        }
    }
}
__global__ void k_fill(const void* __restrict__ ei, int E) {
    int idx = blockIdx.x * blockDim.x + threadIdx.x;
    if (idx < E) {
        int r = edge_at(ei, idx);
        int c = edge_at(ei, (size_t)E + idx);
        if ((unsigned)r < NN && (unsigned)c < NN) {
            int pos = atomicAdd(&g_cur[c], 1);
            g_srce[pos] = r;
        }
    }
}

// ---------------- fused MLP: cp.async double-buffer + tf32 mma (no cvt) ------
// Raw fp32 bits fed to tf32 HMMA (HW reads top bits; truncation vs RN only).
#define TM 128
#define TKC 64
#define NCHUNK (NFEAT / TKC)
#define LDF  68          // fp32 stride: 68 % 32 = 4 -> (4r+q) conflict-free
#define LDA  72          // fp16 Hs stride (halfs)
#define LDW2 65

#define SMO_W2 0                           // 4160 B
#define SMO_A0 4160                        // 128*68*4 = 34816 B
#define SMO_A1 38976                       // 34816 B
#define SMO_B0 73792                       // 64*68*4 = 17408 B
#define SMO_B1 91200                       // 17408 B
#define SM_TOTAL 108608

__device__ __forceinline__ void mma_tf32(float* d, uint32_t a0, uint32_t a1,
                                         uint32_t a2, uint32_t a3,
                                         uint32_t b0, uint32_t b1) {
    asm volatile(
        "mma.sync.aligned.m16n8k8.row.col.f32.tf32.tf32.f32 "
        "{%0,%1,%2,%3}, {%4,%5,%6,%7}, {%8,%9}, {%0,%1,%2,%3};"
        : "+f"(d[0]), "+f"(d[1]), "+f"(d[2]), "+f"(d[3])
        : "r"(a0), "r"(a1), "r"(a2), "r"(a3), "r"(b0), "r"(b1));
}

__global__ __launch_bounds__(256) void k_gemm(const float* __restrict__ x,
                                              const float* __restrict__ W1,
                                              const float* __restrict__ b1,
                                              const float* __restrict__ W2,
                                              const float* __restrict__ b2,
                                              int n) {
    extern __shared__ __align__(16) unsigned char sm[];
    float* W2s = (float*)(sm + SMO_W2);
    const uint32_t smb = smem_u32(sm);

    const int t = threadIdx.x, wid = t >> 5, lane = t & 31;
    const int warpM = wid & 3, warpN = wid >> 2;
    const int r = lane >> 2, q = lane & 3;
    const int nodeBase = blockIdx.x * TM;

    for (int i = t; i < NCLS * NHID; i += 256)
        W2s[(i >> 6) * LDW2 + (i & 63)] = W2[i];

#define ISSUE(c, buf)                                                          \
    {                                                                          \
        uint32_t abase = smb + ((buf) ? SMO_A1 : SMO_A0);                      \
        uint32_t bbase = smb + ((buf) ? SMO_B1 : SMO_B0);                      \
        _Pragma("unroll") for (int i = 0; i < 8; ++i) {                        \
            int slot = t + i * 256;                                            \
            int row = slot >> 4, f4 = slot & 15;                               \
            int gn = nodeBase + row;                                           \
            int gc = (gn < n) ? gn : (n - 1);                                  \
            const float* src = x + (size_t)gc * NFEAT + (c) * TKC + f4 * 4;    \
            CP_ASYNC16(abase + (uint32_t)(row * LDF + f4 * 4) * 4, src,        \
                       (gn < n) ? 16 : 0);                                     \
        }                                                                      \
        _Pragma("unroll") for (int i = 0; i < 4; ++i) {                        \
            int slot = t + i * 256;                                            \
            int row = slot >> 4, f4 = slot & 15;                               \
            const float* src = W1 + (size_t)row * NFEAT + (c) * TKC + f4 * 4;  \
            CP_ASYNC16(bbase + (uint32_t)(row * LDF + f4 * 4) * 4, src, 16);   \
        }                                                                      \
        CP_COMMIT();                                                           \
    }

    float acc[2][4][4];
#pragma unroll
    for (int mt = 0; mt < 2; ++mt)
#pragma unroll
        for (int nt = 0; nt < 4; ++nt)
#pragma unroll
            for (int j = 0; j < 4; ++j) acc[mt][nt][j] = 0.f;

    ISSUE(0, 0);
    ISSUE(1, 1);

    for (int c = 0; c < NCHUNK; ++c) {
        if (c == NCHUNK - 1)
            asm volatile("cp.async.wait_group 0;" ::: "memory");
        else
            asm volatile("cp.async.wait_group 1;" ::: "memory");
        __syncthreads();
        const uint32_t* As = (const uint32_t*)(sm + ((c & 1) ? SMO_A1 : SMO_A0));
        const uint32_t* Bs = (const uint32_t*)(sm + ((c & 1) ? SMO_B1 : SMO_B0));
#pragma unroll
        for (int ks = 0; ks < TKC / 8; ++ks) {
            int kc = ks * 8 + q;
            uint32_t bf[4][2];
#pragma unroll
            for (int nt = 0; nt < 4; ++nt) {
                int nr = warpN * 32 + nt * 8 + r;
                bf[nt][0] = Bs[nr * LDF + kc];       // raw fp32 bits as tf32
                bf[nt][1] = Bs[nr * LDF + kc + 4];
            }
#pragma unroll
            for (int mt = 0; mt < 2; ++mt) {
                int mr = warpM * 32 + mt * 16 + r;
                uint32_t a0 = As[mr * LDF + kc];
                uint32_t a1 = As[(mr + 8) * LDF + kc];
                uint32_t a2 = As[mr * LDF + kc + 4];
                uint32_t a3 = As[(mr + 8) * LDF + kc + 4];
#pragma unroll
                for (int nt = 0; nt < 4; ++nt)
                    mma_tf32(acc[mt][nt], a0, a1, a2, a3, bf[nt][0], bf[nt][1]);
            }
        }
        __syncthreads();
        if (c + 2 < NCHUNK) ISSUE(c + 2, c & 1);
    }

    // ---- epilogue: relu+bias -> Hs fp16 (A0 region), GEMM2, u0 = dis*h0 ----
    __half* Hs = (__half*)(sm + SMO_A0);
#pragma unroll
    for (int mt = 0; mt < 2; ++mt) {
        int r0 = warpM * 32 + mt * 16 + r;
#pragma unroll
        for (int nt = 0; nt < 4; ++nt) {
            int col = warpN * 32 + nt * 8 + q * 2;
            float bb0 = b1[col], bb1 = b1[col + 1];
            float* a = acc[mt][nt];
            __half2 lo = __floats2half2_rn(fmaxf(a[0] + bb0, 0.f), fmaxf(a[1] + bb1, 0.f));
            __half2 hi = __floats2half2_rn(fmaxf(a[2] + bb0, 0.f), fmaxf(a[3] + bb1, 0.f));
            *(__half2*)(Hs + (size_t)r0 * LDA + col)       = lo;
            *(__half2*)(Hs + (size_t)(r0 + 8) * LDA + col) = hi;
        }
    }
    __syncthreads();

    int cls = t & 15, grp = t >> 4;
    float bc = b2[cls];
#pragma unroll
    for (int i = 0; i < 8; ++i) {
        int row = grp * 8 + i;
        int gn = nodeBase + row;
        float a = bc;
        const __half2* hr = (const __half2*)(Hs + (size_t)row * LDA);
#pragma unroll
        for (int k = 0; k < 32; ++k) {
            float2 f = __half22float2(hr[k]);
            a = fmaf(f.x, W2s[cls * LDW2 + 2 * k], a);
            a = fmaf(f.y, W2s[cls * LDW2 + 2 * k + 1], a);
        }
        if (gn < n)
            g_h0h[(size_t)gn * NCLS + cls] = __float2half_rn(a * g_dis[gn]);  // u0
    }
#undef ISSUE
}

// ---------------- APPNP step: 4 lanes/node, shfl-free broadcast edge loads ---
// u_new_c = 0.9*dis_c^2 * (sum_in u_r + u_c) + 0.1*u0_c
__global__ __launch_bounds__(256) void k_prop(int srcSel, int dstSel, int n) {
    int t = blockIdx.x * 256 + threadIdx.x;
    int node = t >> 2, lane = t & 3;
    bool valid = node < n;
    if (!valid) node = n - 1;
    const uint2* __restrict__ hin = (const uint2*)(
        (srcSel == 0) ? g_h0h : ((srcSel == 1) ? g_bufA : g_bufB));
    uint2* __restrict__ hout = (uint2*)((dstSel == 1) ? g_bufA : g_bufB);

    int start = g_ptr[node], end = g_ptr[node + 1];
    float ax0 = 0.f, ax1 = 0.f, ax2 = 0.f, ax3 = 0.f;
    float cx0 = 0.f, cx1 = 0.f, cx2 = 0.f, cx3 = 0.f;

#define GATHER(sv, A0, A1, A2, A3)                                    \
    {                                                                 \
        uint2 u = __ldg(hin + (size_t)(sv) * 4 + lane);               \
        float2 f0 = __half22float2(*(__half2*)&u.x);                  \
        float2 f1 = __half22float2(*(__half2*)&u.y);                  \
        A0 += f0.x; A1 += f0.y; A2 += f1.x; A3 += f1.y;               \
    }

    for (int base = start; base < end; base += 8) {
        int s0 = __ldg(&g_srce[base]);
        int s1 = (base + 1 < end) ? __ldg(&g_srce[base + 1]) : -1;
        int s2 = (base + 2 < end) ? __ldg(&g_srce[base + 2]) : -1;
        int s3 = (base + 3 < end) ? __ldg(&g_srce[base + 3]) : -1;
        int s4 = (base + 4 < end) ? __ldg(&g_srce[base + 4]) : -1;
        int s5 = (base + 5 < end) ? __ldg(&g_srce[base + 5]) : -1;
        int s6 = (base + 6 < end) ? __ldg(&g_srce[base + 6]) : -1;
        int s7 = (base + 7 < end) ? __ldg(&g_srce[base + 7]) : -1;
        GATHER(s0, ax0, ax1, ax2, ax3);
        if (s1 >= 0) GATHER(s1, cx0, cx1, cx2, cx3);
        if (s2 >= 0) GATHER(s2, ax0, ax1, ax2, ax3);
        if (s3 >= 0) GATHER(s3, cx0, cx1, cx2, cx3);
        if (s4 >= 0) GATHER(s4, ax0, ax1, ax2, ax3);
        if (s5 >= 0) GATHER(s5, cx0, cx1, cx2, cx3);
        if (s6 >= 0) GATHER(s6, ax0, ax1, ax2, ax3);
        if (s7 >= 0) GATHER(s7, cx0, cx1, cx2, cx3);
    }
#undef GATHER
    ax0 += cx0; ax1 += cx1; ax2 += cx2; ax3 += cx3;
    {
        uint2 u = hin[(size_t)node * 4 + lane];          // self loop (u_c)
        float2 f0 = __half22float2(*(__half2*)&u.x);
        float2 f1 = __half22float2(*(__half2*)&u.y);
        ax0 += f0.x; ax1 += f0.y; ax2 += f1.x; ax3 += f1.y;
    }
    float dv = g_dis[node];
    float s = 0.9f * dv * dv;
    uint2 uz = ((const uint2*)g_h0h)[(size_t)node * 4 + lane];
    float2 z0 = __half22float2(*(__half2*)&uz.x);
    float2 z1 = __half22float2(*(__half2*)&uz.y);
    float r0 = fmaf(s, ax0, 0.1f * z0.x);
    float r1 = fmaf(s, ax1, 0.1f * z0.y);
    float r2 = fmaf(s, ax2, 0.1f * z1.x);
    float r3 = fmaf(s, ax3, 0.1f * z1.y);
    if (valid) {
        uint2 o;
        o.x = h2u(__floats2half2_rn(r0, r1));
        o.y = h2u(__floats2half2_rn(r2, r3));
        hout[(size_t)node * 4 + lane] = o;
    }
}

// ---------------- log-softmax (thread per node, un-scale u -> h) -------------
__global__ void k_lsm(float* __restrict__ out, int n) {
    int nd = blockIdx.x * blockDim.x + threadIdx.x;
    if (nd >= n) return;
    const __half2* hb = (const __half2*)g_bufB + (size_t)nd * 8;
    float inv = 1.0f / g_dis[nd];
    float v[16];
#pragma unroll
    for (int i = 0; i < 8; ++i) {
        float2 f = __half22float2(hb[i]);
        v[2 * i] = f.x * inv;
        v[2 * i + 1] = f.y * inv;
    }
    float m = v[0];
#pragma unroll
    for (int i = 1; i < 16; ++i) m = fmaxf(m, v[i]);
    float s = 0.f;
#pragma unroll
    for (int i = 0; i < 16; ++i) s += expf(v[i] - m);
    float ls = m + logf(s);
    float* o = out + (size_t)nd * 16;
#pragma unroll
    for (int i = 0; i < 16; i += 4) {
        float4 qv = make_float4(v[i] - ls, v[i + 1] - ls, v[i + 2] - ls, v[i + 3] - ls);
        *(float4*)(o + i) = qv;
    }
}

// ---------------- launch (serial, single stream) -----------------------------
extern "C" void kernel_launch(void* const* d_in, const int* in_sizes, int n_in,
                              void* d_out, int out_size) {
    const float* x  = (const float*)d_in[0];
    const float* W1 = (const float*)d_in[1];
    const float* b1 = (const float*)d_in[2];
    const float* W2 = (const float*)d_in[3];
    const float* b2 = (const float*)d_in[4];
    const void*  ei = d_in[5];
    float* out = (float*)d_out;

    int N = in_sizes[0] / NFEAT;
    int E = in_sizes[5] / 2;
    int sblocks = (N + SCAN_ELEMS - 1) / SCAN_ELEMS;

    static int attr_set = 0;
    if (!attr_set) {
        cudaFuncSetAttribute(k_gemm, cudaFuncAttributeMaxDynamicSharedMemorySize,
                             SM_TOTAL);
        attr_set = 1;
    }

    // launch index 3 (ncu capture) = k_gemm
    k_initdetect<<<(N + 255) / 256, 256>>>((const int*)ei, E, N);       // 0
    k_count<<<(E + 255) / 256, 256>>>(ei, E);                           // 1
    k_scan1<<<sblocks, SCAN_T>>>(N);                                    // 2
    k_gemm<<<(N + TM - 1) / TM, 256, SM_TOTAL>>>(x, W1, b1, W2, b2, N); // 3
    k_scan3<<<sblocks, SCAN_T>>>(sblocks, N);                           // 4
    k_fill<<<(E + 255) / 256, 256>>>(ei, E);                            // 5

    int grid = (N * 4 + 255) / 256;
    int src = 0;
    for (int step = 1; step <= 10; ++step) {
        int dst = (step & 1) ? 1 : 2;
        k_prop<<<grid, 256>>>(src, dst, N);
        src = dst;
    }
    k_lsm<<<(N + 255) / 256, 256>>>(out, N);
}